// round 1
// baseline (speedup 1.0000x reference)
#include <cuda_runtime.h>
#include <math.h>

#define N 4096
#define D 128
#define NCLS 512
#define L 1601          // NUM_BINS + 1
#define HPAD 1604       // padded histogram stride

// ---- device scratch (allocation-free rule: __device__ globals) ----
__device__ float g_sim[(size_t)N * N];   // 64 MB similarity scratch
__device__ float g_loss[N];
__device__ float g_reward[N];
__device__ int   g_cntR[NCLS];           // counts of targets_row
__device__ int   g_cntL[NCLS];           // counts of reward_labels

// order-preserving float<->uint for atomicMax on floats (incl. negatives/-inf)
__device__ __forceinline__ unsigned fenc(float x){
    unsigned u = __float_as_uint(x);
    return (u & 0x80000000u) ? ~u : (u | 0x80000000u);
}
__device__ __forceinline__ float fdec(unsigned e){
    unsigned u = (e & 0x80000000u) ? (e & 0x7FFFFFFFu) : ~e;
    return __uint_as_float(u);
}

// ---------------- kernel 0: class counts ----------------
__global__ void count_kernel(const int* __restrict__ tr, const int* __restrict__ rl){
    __shared__ int cR[NCLS], cL[NCLS];
    int t = threadIdx.x;
    for (int i = t; i < NCLS; i += blockDim.x){ cR[i] = 0; cL[i] = 0; }
    __syncthreads();
    for (int i = t; i < N; i += blockDim.x){
        atomicAdd(&cR[tr[i]], 1);
        atomicAdd(&cL[rl[i]], 1);
    }
    __syncthreads();
    for (int i = t; i < NCLS; i += blockDim.x){ g_cntR[i] = cR[i]; g_cntL[i] = cL[i]; }
}

// ---------------- kernel 1: loss rows ----------------
// Each block owns 16 full rows: GEMM pass (writes sim to global, tracks per-row
// pos/neg maxima), then threshold pass re-reading the (L2-hot) sim rows.
#define LROWS 16
#define LCOLS 256
#define LKC   32
#define LBSTR 260

__global__ __launch_bounds__(256) void loss_kernel(
    const float* __restrict__ A, const int* __restrict__ tc,
    const float* __restrict__ B, const int* __restrict__ tr)
{
    __shared__ float As[LROWS][33];
    __shared__ float Bs[LKC][LBSTR];
    __shared__ int trs[LCOLS];
    __shared__ int tcs[LROWS];
    __shared__ unsigned pmax_s[LROWS], nmax_s[LROWS];
    __shared__ float pthr_s[LROWS], nthr_s[LROWS];
    __shared__ float ploss_s[LROWS], nloss_s[LROWS];

    const int tid  = threadIdx.x;
    const int rg   = tid >> 6;    // 0..3  (4 rows each)
    const int cg   = tid & 63;    // 0..63 (4 cols each)
    const int row0 = blockIdx.x * LROWS;

    if (tid < LROWS){
        tcs[tid]     = tc[row0 + tid];
        pmax_s[tid]  = fenc(-INFINITY);
        nmax_s[tid]  = fenc(-INFINITY);
        ploss_s[tid] = 0.f;
        nloss_s[tid] = 0.f;
    }
    __syncthreads();

    float lp[4], ln[4];
#pragma unroll
    for (int r = 0; r < 4; r++){ lp[r] = -INFINITY; ln[r] = -INFINITY; }

    for (int jt = 0; jt < N; jt += LCOLS){
        trs[tid] = tr[jt + tid];

        float acc[4][4];
#pragma unroll
        for (int r = 0; r < 4; r++)
#pragma unroll
            for (int c = 0; c < 4; c++) acc[r][c] = 0.f;

#pragma unroll
        for (int kc = 0; kc < D; kc += LKC){
            for (int i = tid; i < LROWS * LKC; i += 256){
                int r = i >> 5, kk = i & 31;
                As[r][kk] = A[(size_t)(row0 + r) * D + kc + kk];
            }
            for (int i = tid; i < LCOLS * (LKC / 4); i += 256){
                int col = i >> 3, k4 = i & 7;
                float4 v = *(const float4*)(B + (size_t)(jt + col) * D + kc + k4 * 4);
                Bs[k4*4+0][col] = v.x; Bs[k4*4+1][col] = v.y;
                Bs[k4*4+2][col] = v.z; Bs[k4*4+3][col] = v.w;
            }
            __syncthreads();
#pragma unroll
            for (int kk = 0; kk < LKC; kk++){
                float4 b = *(const float4*)&Bs[kk][cg * 4];
                float a0 = As[rg*4+0][kk], a1 = As[rg*4+1][kk];
                float a2 = As[rg*4+2][kk], a3 = As[rg*4+3][kk];
                acc[0][0] += a0*b.x; acc[0][1] += a0*b.y; acc[0][2] += a0*b.z; acc[0][3] += a0*b.w;
                acc[1][0] += a1*b.x; acc[1][1] += a1*b.y; acc[1][2] += a1*b.z; acc[1][3] += a1*b.w;
                acc[2][0] += a2*b.x; acc[2][1] += a2*b.y; acc[2][2] += a2*b.z; acc[2][3] += a2*b.w;
                acc[3][0] += a3*b.x; acc[3][1] += a3*b.y; acc[3][2] += a3*b.z; acc[3][3] += a3*b.w;
            }
            __syncthreads();
        }

        // epilogue: maxima + sim store
#pragma unroll
        for (int r = 0; r < 4; r++){
            int gi  = row0 + rg * 4 + r;
            int tcv = tcs[rg * 4 + r];
#pragma unroll
            for (int c = 0; c < 4; c++){
                int j   = jt + cg * 4 + c;
                float s = acc[r][c];
                if (trs[cg * 4 + c] == tcv){
                    if (j != gi) lp[r] = fmaxf(lp[r], s);   // pos excludes diagonal
                } else {
                    ln[r] = fmaxf(ln[r], s);                // neg keeps diagonal
                }
            }
            *(float4*)(g_sim + (size_t)gi * N + jt + cg * 4) =
                make_float4(acc[r][0], acc[r][1], acc[r][2], acc[r][3]);
        }
        __syncthreads();
    }

#pragma unroll
    for (int r = 0; r < 4; r++){
        atomicMax(&pmax_s[rg*4+r], fenc(lp[r]));
        atomicMax(&nmax_s[rg*4+r], fenc(ln[r]));
    }
    __syncthreads();
    if (tid < LROWS){
        float pm = fdec(pmax_s[tid]);
        float nm = fdec(nmax_s[tid]);
        nthr_s[tid] = nm + 0.1f;                 // pos selected iff sim < neg_max + margin
        pthr_s[tid] = fmaxf(0.6f, pm) - 0.1f;    // neg selected iff sim > max(0.6,pos_max)-margin
    }
    __syncthreads();

    // pass B: thresholded sums over stored sim (L2 hot)
    float plr[LROWS], nlr[LROWS];
#pragma unroll
    for (int r = 0; r < LROWS; r++){ plr[r] = 0.f; nlr[r] = 0.f; }

    for (int jt = 0; jt < N; jt += 256){
        int j   = jt + tid;
        int lbl = tr[j];
#pragma unroll
        for (int r = 0; r < LROWS; r++){
            float s = g_sim[(size_t)(row0 + r) * N + j];
            if (lbl == tcs[r]){
                if (j != row0 + r && s < nthr_s[r]) plr[r] += 1.0f - s;
            } else {
                if (s > pthr_s[r]) nlr[r] += s;
            }
        }
    }
#pragma unroll
    for (int r = 0; r < LROWS; r++){
        atomicAdd(&ploss_s[r], plr[r]);
        atomicAdd(&nloss_s[r], nlr[r]);
    }
    __syncthreads();
    if (tid < LROWS){
        int gi   = row0 + tid;
        int tcv  = tcs[tid];
        int npos = g_cntR[tcv] - ((tr[gi] == tcv) ? 1 : 0);
        g_loss[gi] = (npos > 0) ? (ploss_s[tid] + nloss_s[tid]) : 0.f;
    }
}

// ---------------- kernel 2: FastAP rewards ----------------
// 8 rows/block, fused GEMM(X Xᵀ) -> soft histogram (shared atomics) -> scan/AP.
#define RROWS 8
#define RCOLS 512
#define RKC   32
#define RBSTR 516
#define INV_DELTA 400.0f

#define RSMEM_BYTES ((2*RROWS*HPAD + RKC*RBSTR + RROWS*33) * 4 + (RCOLS + RROWS) * 4)

__global__ __launch_bounds__(256) void reward_kernel(
    const float* __restrict__ X, const int* __restrict__ rl)
{
    extern __shared__ unsigned char smem_raw[];
    float* hp   = (float*)smem_raw;          // [RROWS][HPAD]
    float* hn   = hp + RROWS * HPAD;         // [RROWS][HPAD]
    float* Bs   = hn + RROWS * HPAD;         // [RKC][RBSTR]
    float* As   = Bs + RKC * RBSTR;          // [RROWS][33]
    int*   rls  = (int*)(As + RROWS * 33);   // [RCOLS]
    int*   rlrow = rls + RCOLS;              // [RROWS]

    const int tid  = threadIdx.x;
    const int rg   = tid >> 7;     // 0..1   (4 rows each)
    const int cg   = tid & 127;    // 0..127 (4 cols each)
    const int row0 = blockIdx.x * RROWS;

    for (int i = tid; i < RROWS * HPAD; i += 256){ hp[i] = 0.f; hn[i] = 0.f; }
    if (tid < RROWS) rlrow[tid] = rl[row0 + tid];
    __syncthreads();

    for (int jt = 0; jt < N; jt += RCOLS){
        rls[tid]       = rl[jt + tid];
        rls[tid + 256] = rl[jt + tid + 256];

        float acc[4][4];
#pragma unroll
        for (int r = 0; r < 4; r++)
#pragma unroll
            for (int c = 0; c < 4; c++) acc[r][c] = 0.f;

#pragma unroll
        for (int kc = 0; kc < D; kc += RKC){
            for (int i = tid; i < RROWS * RKC; i += 256){
                int r = i >> 5, kk = i & 31;
                As[r * 33 + kk] = X[(size_t)(row0 + r) * D + kc + kk];
            }
            for (int i = tid; i < RCOLS * (RKC / 4); i += 256){
                int col = i >> 3, k4 = i & 7;
                float4 v = *(const float4*)(X + (size_t)(jt + col) * D + kc + k4 * 4);
                Bs[(k4*4+0)*RBSTR + col] = v.x; Bs[(k4*4+1)*RBSTR + col] = v.y;
                Bs[(k4*4+2)*RBSTR + col] = v.z; Bs[(k4*4+3)*RBSTR + col] = v.w;
            }
            __syncthreads();
#pragma unroll
            for (int kk = 0; kk < RKC; kk++){
                float4 b = *(const float4*)&Bs[kk * RBSTR + cg * 4];
                float a0 = As[(rg*4+0)*33 + kk], a1 = As[(rg*4+1)*33 + kk];
                float a2 = As[(rg*4+2)*33 + kk], a3 = As[(rg*4+3)*33 + kk];
                acc[0][0] += a0*b.x; acc[0][1] += a0*b.y; acc[0][2] += a0*b.z; acc[0][3] += a0*b.w;
                acc[1][0] += a1*b.x; acc[1][1] += a1*b.y; acc[1][2] += a1*b.z; acc[1][3] += a1*b.w;
                acc[2][0] += a2*b.x; acc[2][1] += a2*b.y; acc[2][2] += a2*b.z; acc[2][3] += a2*b.w;
                acc[3][0] += a3*b.x; acc[3][1] += a3*b.y; acc[3][2] += a3*b.z; acc[3][3] += a3*b.w;
            }
            __syncthreads();
        }

        // epilogue: soft-histogram scatter
#pragma unroll
        for (int r = 0; r < 4; r++){
            int lr = rg * 4 + r;
            int gi = row0 + lr;
            int li = rlrow[lr];
            float* hpr = hp + lr * HPAD;
            float* hnr = hn + lr * HPAD;
#pragma unroll
            for (int c = 0; c < 4; c++){
                int j = jt + cg * 4 + c;
                if (j == gi) continue;                     // eye excluded from both
                float s  = acc[r][c];
                float d2 = fminf(fmaxf(2.0f - 2.0f * s, 0.0f), 4.0f);
                float t  = d2 * INV_DELTA;
                float fl = floorf(t);
                int i0 = (int)fl; if (i0 > 1600) i0 = 1600;
                int i1 = i0 + 1;  if (i1 > 1600) i1 = 1600;
                float fr = t - fl;
                float* h = (rls[cg * 4 + c] == li) ? hpr : hnr;
                atomicAdd(h + i0, 1.0f - fr);
                atomicAdd(h + i1, fr);
            }
        }
        __syncthreads();
    }

    // per-row prefix scan + AP (one warp per row)
    const int warp = tid >> 5;
    const int lane = tid & 31;
    const float* p = hp + warp * HPAD;
    const float* q = hn + warp * HPAD;
    float cp = 0.f, cs = 0.f, ap = 0.f;
    for (int base = 0; base < L; base += 32){
        int b = base + lane;
        float pv = (b < L) ? p[b] : 0.f;
        float sv = pv + ((b < L) ? q[b] : 0.f);
        float P = pv, S = sv;
#pragma unroll
        for (int o = 1; o < 32; o <<= 1){
            float tP = __shfl_up_sync(0xFFFFFFFFu, P, o);
            float tS = __shfl_up_sync(0xFFFFFFFFu, S, o);
            if (lane >= o){ P += tP; S += tS; }
        }
        float Hp = cp + P;
        float Ha = cs + S;
        if (b < L && Ha > 0.f) ap += pv * Hp / Ha;
        cp += __shfl_sync(0xFFFFFFFFu, P, 31);
        cs += __shfl_sync(0xFFFFFFFFu, S, 31);
    }
#pragma unroll
    for (int o = 16; o; o >>= 1) ap += __shfl_down_sync(0xFFFFFFFFu, ap, o);
    if (lane == 0){
        int gi = row0 + warp;
        int np = g_cntL[rlrow[warp]] - 1;
        g_reward[gi] = (np > 0) ? ap / (float)np : 0.f;
    }
}

// ---------------- kernel 3: final scalar ----------------
__global__ void final_kernel(float* __restrict__ out){
    __shared__ float red[32];
    float s = 0.f;
    for (int i = threadIdx.x; i < N; i += blockDim.x)
        s += g_loss[i] * (1.0f - g_reward[i]);
#pragma unroll
    for (int o = 16; o; o >>= 1) s += __shfl_down_sync(0xFFFFFFFFu, s, o);
    int warp = threadIdx.x >> 5, lane = threadIdx.x & 31;
    if (lane == 0) red[warp] = s;
    __syncthreads();
    if (warp == 0){
        s = (lane < (int)(blockDim.x >> 5)) ? red[lane] : 0.f;
#pragma unroll
        for (int o = 16; o; o >>= 1) s += __shfl_down_sync(0xFFFFFFFFu, s, o);
        if (lane == 0) out[0] = s / (float)N;
    }
}

// ---------------- launch ----------------
extern "C" void kernel_launch(void* const* d_in, const int* in_sizes, int n_in,
                              void* d_out, int out_size)
{
    const float* inputs_col    = (const float*)d_in[0];
    const int*   targets_col   = (const int*)  d_in[1];
    const float* inputs_row    = (const float*)d_in[2];
    const int*   targets_row   = (const int*)  d_in[3];
    const int*   reward_labels = (const int*)  d_in[4];
    float* out = (float*)d_out;

    cudaFuncSetAttribute(reward_kernel,
                         cudaFuncAttributeMaxDynamicSharedMemorySize, RSMEM_BYTES);

    count_kernel<<<1, 512>>>(targets_row, reward_labels);
    loss_kernel<<<N / LROWS, 256>>>(inputs_col, targets_col, inputs_row, targets_row);
    reward_kernel<<<N / RROWS, 256, RSMEM_BYTES>>>(inputs_col, reward_labels);
    final_kernel<<<1, 256>>>(out);
}